// round 5
// baseline (speedup 1.0000x reference)
#include <cuda_runtime.h>
#include <math.h>

#define B_   8
#define T_   64
#define CIN_ 64
#define L_   256
#define F_   128
#define CO_  512   // 4*F

// Scratch (device globals — no runtime allocation allowed).
__device__ float g_Ax0[(size_t)512 * CO_ * L_];   // layer0 input-conv, n = b*T+t
__device__ float g_Ax1[(size_t)512 * CO_ * L_];   // layer1 input-conv, n = t*B+b
__device__ float g_hs0[(size_t)T_ * B_ * F_ * L_];
__device__ float g_c0s[(size_t)B_ * F_ * L_];
__device__ float g_c1s[(size_t)B_ * F_ * L_];

__device__ __forceinline__ float sigm(float x) { return 1.0f / (1.0f + expf(-x)); }

__device__ __forceinline__ unsigned long long bcast2(float v) {
    unsigned long long r;
    asm("mov.b64 %0, {%1, %1};" : "=l"(r) : "f"(v));
    return r;
}
__device__ __forceinline__ float2 unpack2(unsigned long long p) {
    float2 r;
    asm("mov.b64 {%0, %1}, %2;" : "=f"(r.x), "=f"(r.y) : "l"(p));
    return r;
}
#define FMA2(acc, w, x) \
    asm("fma.rn.f32x2 %0, %1, %2, %0;" : "+l"(acc) : "l"(w), "l"(x))

extern __shared__ char dynsmem[];
#define CONV_SMEM (2*80*16*16 + 2*16*136*4)   // 58368 B (max of both bodies)

// ---------------------------------------------------------------------------
// Conv body. Tile 64 co x 128 l, 256 thr, thread 4co x 8l. Double-buffered.
// Xn = Xbase + bz*xStrideZ ; out row base = outBase + bz*oStrideZ.
// ---------------------------------------------------------------------------
__device__ __forceinline__ void conv_body(
    const float* __restrict__ Xbase, size_t xStrideZ,
    const float* __restrict__ W,     // [CO, CW, 5]
    const float* __restrict__ bias,  // [CO]
    float* __restrict__ outBase, size_t oStrideZ,
    int Cx, int CW, int c0w,
    int bx, int by, int bz)
{
    float4* Wsm = (float4*)dynsmem;                              // [2][80][16]
    float*  Xsm = (float*)(dynsmem + 2*80*16*sizeof(float4));    // [2][16][136]

    const int tid = threadIdx.x;
    const int tx = tid & 15, ty = tid >> 4;
    const int l0  = bx * 128;
    const int co0 = by * 64;
    const float* Xn = Xbase + (size_t)bz * xStrideZ;

    const int wRow = tid >> 2, wPart = tid & 3;
    const int nCh = Cx >> 4;

    unsigned long long accp[2][8];
    #pragma unroll
    for (int p = 0; p < 2; p++)
        #pragma unroll
        for (int j = 0; j < 8; j++) accp[p][j] = 0ULL;

    float4 wv[5];
    float  xv[9];

    auto ldW = [&](int ch) {
        const float4* wp = (const float4*)(W + (size_t)(co0 + wRow) * CW * 5
                                             + (size_t)(c0w + (ch << 4)) * 5 + wPart * 20);
        #pragma unroll
        for (int e = 0; e < 5; e++) wv[e] = wp[e];
    };
    auto ldX = [&](int ch) {
        const float* Xc = Xn + (size_t)(ch << 4) * L_;
        #pragma unroll
        for (int r = 0; r < 9; r++) {
            int i = tid + (r << 8);
            if (i < 16 * 132) {
                int ci = i / 132, col = i - ci * 132;
                int gl = l0 + col - 2;
                xv[r] = (gl >= 0 && gl < L_) ? Xc[(size_t)ci * L_ + gl] : 0.f;
            }
        }
    };
    auto stWX = [&](int buf) {
        float4* Wb = Wsm + buf * 80 * 16;
        float*  Xb = Xsm + buf * 16 * 136;
        #pragma unroll
        for (int e = 0; e < 5; e++) {
            const float* f = (const float*)&wv[e];
            #pragma unroll
            for (int j = 0; j < 4; j++)
                ((float*)&Wb[(wPart * 20 + e * 4 + j) * 16 + (wRow >> 2)])[wRow & 3] = f[j];
        }
        #pragma unroll
        for (int r = 0; r < 9; r++) {
            int i = tid + (r << 8);
            if (i < 16 * 132) {
                int ci = i / 132;
                Xb[ci * 136 + (i - ci * 132)] = xv[r];
            }
        }
    };
    auto compute = [&](int buf) {
        const float4* Wb = Wsm + buf * 80 * 16;
        const float*  Xb = Xsm + buf * 16 * 136;
        #pragma unroll
        for (int ci = 0; ci < 16; ci++) {
            const float* row = Xb + ci * 136 + tx * 8;
            float4 q0 = *(const float4*)(row);
            float4 q1 = *(const float4*)(row + 4);
            float4 q2 = *(const float4*)(row + 8);
            float xr[12] = {q0.x,q0.y,q0.z,q0.w, q1.x,q1.y,q1.z,q1.w, q2.x,q2.y,q2.z,q2.w};
            unsigned long long xb[12];
            #pragma unroll
            for (int j = 0; j < 12; j++) xb[j] = bcast2(xr[j]);
            #pragma unroll
            for (int k = 0; k < 5; k++) {
                ulonglong2 wp = *(const ulonglong2*)&Wb[(ci * 5 + k) * 16 + ty];
                #pragma unroll
                for (int jl = 0; jl < 8; jl++) {
                    FMA2(accp[0][jl], wp.x, xb[jl + k]);
                    FMA2(accp[1][jl], wp.y, xb[jl + k]);
                }
            }
        }
    };

    ldW(0); ldX(0); stWX(0);
    __syncthreads();
    #pragma unroll 1
    for (int ch = 0; ch < nCh; ch++) {
        bool more = (ch + 1) < nCh;
        if (more) { ldW(ch + 1); ldX(ch + 1); }
        compute(ch & 1);
        if (more) stWX((ch + 1) & 1);
        __syncthreads();
    }

    #pragma unroll
    for (int p = 0; p < 2; p++) {
        float o[2][8];
        #pragma unroll
        for (int jl = 0; jl < 8; jl++) {
            float2 v = unpack2(accp[p][jl]);
            o[0][jl] = v.x; o[1][jl] = v.y;
        }
        #pragma unroll
        for (int q = 0; q < 2; q++) {
            int co = co0 + ty * 4 + p * 2 + q;
            float bv = bias[co];
            float* op = outBase + (size_t)bz * oStrideZ + (size_t)co * L_ + l0 + tx * 8;
            *(float4*)(op)     = make_float4(o[q][0]+bv, o[q][1]+bv, o[q][2]+bv, o[q][3]+bv);
            *(float4*)(op + 4) = make_float4(o[q][4]+bv, o[q][5]+bv, o[q][6]+bv, o[q][7]+bv);
        }
    }
}

// ---------------------------------------------------------------------------
// LSTM step body. Tile 16f x 4gates x 64l, 256 thr. Double-buffered +
// epilogue operand prefetch during last chunk.
// ---------------------------------------------------------------------------
__device__ __forceinline__ void lstm_body(
    const float* __restrict__ Hprev, // [B, F, L]
    const float* __restrict__ W,     // [CO, CW, 5]
    const float* __restrict__ Ax_t,  // base for this timestep
    size_t axStrideB,
    const float* __restrict__ Cprev, // [B, F, L]
    float* __restrict__ Cout,        // [B, F, L]
    float* __restrict__ Hout,        // [B, F, L]
    int CW, int choff,
    int bx, int by, int bz)
{
    float4* Wsm = (float4*)dynsmem;                              // [2][80][16]
    float*  Xsm = (float*)(dynsmem + 2*80*16*sizeof(float4));    // [2][16][72]

    const int tid = threadIdx.x;
    const int tx = tid & 15, ty = tid >> 4;
    const int l0 = bx * 64;
    const int f0 = by * 16;
    const int b  = bz;
    const float* Hb = Hprev + (size_t)b * F_ * L_;

    unsigned long long accp[2][4];
    #pragma unroll
    for (int p = 0; p < 2; p++)
        #pragma unroll
        for (int j = 0; j < 4; j++) accp[p][j] = 0ULL;

    const int wRow = tid >> 2, wPart = tid & 3;
    const int gW = wRow >> 4, flW = wRow & 15;
    const int coW = gW * F_ + f0 + flW;

    float4 wv[5];
    float  xv[5];

    auto ldW = [&](int ch) {
        const float4* wp = (const float4*)(W + (size_t)coW * CW * 5
                                             + (size_t)(choff + (ch << 4)) * 5 + wPart * 20);
        #pragma unroll
        for (int e = 0; e < 5; e++) wv[e] = wp[e];
    };
    auto ldX = [&](int ch) {
        const float* Hc = Hb + (size_t)(ch << 4) * L_;
        #pragma unroll
        for (int r = 0; r < 5; r++) {
            int i = tid + (r << 8);
            if (i < 16 * 68) {
                int ci = i / 68, col = i - ci * 68;
                int gl = l0 + col - 2;
                xv[r] = (gl >= 0 && gl < L_) ? Hc[(size_t)ci * L_ + gl] : 0.f;
            }
        }
    };
    auto stWX = [&](int buf) {
        float4* Wb = Wsm + buf * 80 * 16;
        float*  Xb = Xsm + buf * 16 * 72;
        #pragma unroll
        for (int e = 0; e < 5; e++) {
            const float* f = (const float*)&wv[e];
            #pragma unroll
            for (int j = 0; j < 4; j++)
                ((float*)&Wb[(wPart * 20 + e * 4 + j) * 16 + flW])[gW] = f[j];
        }
        #pragma unroll
        for (int r = 0; r < 5; r++) {
            int i = tid + (r << 8);
            if (i < 16 * 68) {
                int ci = i / 68;
                Xb[ci * 72 + (i - ci * 68)] = xv[r];
            }
        }
    };
    auto compute = [&](int buf) {
        const float4* Wb = Wsm + buf * 80 * 16;
        const float*  Xb = Xsm + buf * 16 * 72;
        #pragma unroll
        for (int ci = 0; ci < 16; ci++) {
            const float* row = Xb + ci * 72 + tx * 4;
            float4 q0 = *(const float4*)(row);
            float4 q1 = *(const float4*)(row + 4);
            float xr[8] = {q0.x,q0.y,q0.z,q0.w, q1.x,q1.y,q1.z,q1.w};
            unsigned long long xb[8];
            #pragma unroll
            for (int j = 0; j < 8; j++) xb[j] = bcast2(xr[j]);
            #pragma unroll
            for (int k = 0; k < 5; k++) {
                ulonglong2 wp = *(const ulonglong2*)&Wb[(ci * 5 + k) * 16 + ty];
                #pragma unroll
                for (int jl = 0; jl < 4; jl++) {
                    FMA2(accp[0][jl], wp.x, xb[jl + k]);
                    FMA2(accp[1][jl], wp.y, xb[jl + k]);
                }
            }
        }
    };

    const int f = f0 + ty;
    const int l = l0 + tx * 4;
    const float* axb = Ax_t + (size_t)b * axStrideB + (size_t)f * L_ + l;
    const size_t idx = ((size_t)b * F_ + f) * L_ + l;
    float4 A0, A1, A2, A3, cp;

    ldW(0); ldX(0); stWX(0);
    __syncthreads();
    #pragma unroll 1
    for (int ch = 0; ch < (F_ >> 4); ch++) {
        bool more = (ch + 1) < (F_ >> 4);
        if (more) {
            ldW(ch + 1); ldX(ch + 1);
        } else {
            A0 = *(const float4*)(axb + (size_t)0 * F_ * L_);
            A1 = *(const float4*)(axb + (size_t)1 * F_ * L_);
            A2 = *(const float4*)(axb + (size_t)2 * F_ * L_);
            A3 = *(const float4*)(axb + (size_t)3 * F_ * L_);
            cp = *(const float4*)&Cprev[idx];
        }
        compute(ch & 1);
        if (more) stWX((ch + 1) & 1);
        __syncthreads();
    }

    float acc[4][4];
    #pragma unroll
    for (int p = 0; p < 2; p++)
        #pragma unroll
        for (int jl = 0; jl < 4; jl++) {
            float2 v = unpack2(accp[p][jl]);
            acc[2 * p][jl]     = v.x;
            acc[2 * p + 1][jl] = v.y;
        }

    float Ai[4] = {A0.x+acc[0][0], A0.y+acc[0][1], A0.z+acc[0][2], A0.w+acc[0][3]};
    float Af[4] = {A1.x+acc[1][0], A1.y+acc[1][1], A1.z+acc[1][2], A1.w+acc[1][3]};
    float Ao[4] = {A2.x+acc[2][0], A2.y+acc[2][1], A2.z+acc[2][2], A2.w+acc[2][3]};
    float Ag[4] = {A3.x+acc[3][0], A3.y+acc[3][1], A3.z+acc[3][2], A3.w+acc[3][3]};
    float cpv[4] = {cp.x, cp.y, cp.z, cp.w};

    float cn[4], hn[4];
    #pragma unroll
    for (int jl = 0; jl < 4; jl++) {
        float ig = sigm(Ai[jl]);
        float fg = sigm(Af[jl]);
        float og = sigm(Ao[jl]);
        float gg = tanhf(Ag[jl]);
        cn[jl] = fg * cpv[jl] + ig * gg;
        hn[jl] = og * tanhf(cn[jl]);
    }
    *(float4*)&Cout[idx] = make_float4(cn[0], cn[1], cn[2], cn[3]);
    *(float4*)&Hout[idx] = make_float4(hn[0], hn[1], hn[2], hn[3]);
}

// ---------------------------------------------------------------------------
// Wavefront kernel: one launch per virtual time tau. Independent roles:
//   [0,256)   layer0 LSTM step t=tau
//   [256,384) conv0 (Ax0) for t=tau+1
//   [384,512) conv1 (Ax1) for t=tau-1   (reads hs0[t] from prev launch)
//   [512,768) layer1 LSTM step t=tau-2
// ---------------------------------------------------------------------------
__global__ __launch_bounds__(256, 2) void wave_kernel(
    const float* __restrict__ x,
    const float* __restrict__ W0, const float* __restrict__ b0,
    const float* __restrict__ W1, const float* __restrict__ b1,
    const float* __restrict__ h0i, const float* __restrict__ c0i,
    const float* __restrict__ h1i, const float* __restrict__ c1i,
    float* __restrict__ Ax0, float* __restrict__ Ax1,
    float* __restrict__ hs0, float* __restrict__ c0s, float* __restrict__ c1s,
    float* __restrict__ out, int tau)
{
    const size_t BFL = (size_t)B_ * F_ * L_;
    const int bid = blockIdx.x;

    if (bid < 256) {
        int t = tau;
        if (t < 0 || t >= T_) return;
        int bx = bid & 3, by = (bid >> 2) & 7, bz = bid >> 5;
        const float* Hp = (t == 0) ? h0i : hs0 + (size_t)(t - 1) * BFL;
        const float* Cp = (t == 0) ? c0i : c0s;
        lstm_body(Hp, W0,
                  Ax0 + (size_t)t * CO_ * L_, (size_t)T_ * CO_ * L_,
                  Cp, c0s, hs0 + (size_t)t * BFL,
                  CIN_ + F_, CIN_, bx, by, bz);
    } else if (bid < 384) {
        int t = tau + 1;
        if (t < 0 || t >= T_) return;
        int b2 = bid - 256;
        int bx = b2 & 1, by = (b2 >> 1) & 7, bz = b2 >> 4;
        conv_body(x + (size_t)t * CIN_ * L_, (size_t)T_ * CIN_ * L_,
                  W0, b0,
                  Ax0 + (size_t)t * CO_ * L_, (size_t)T_ * CO_ * L_,
                  CIN_, CIN_ + F_, 0, bx, by, bz);
    } else if (bid < 512) {
        int t = tau - 1;
        if (t < 0 || t >= T_) return;
        int b2 = bid - 384;
        int bx = b2 & 1, by = (b2 >> 1) & 7, bz = b2 >> 4;
        conv_body(hs0 + (size_t)t * BFL, (size_t)F_ * L_,
                  W1, b1,
                  Ax1 + (size_t)t * B_ * CO_ * L_, (size_t)CO_ * L_,
                  F_, 2 * F_, 0, bx, by, bz);
    } else {
        int t = tau - 2;
        if (t < 0 || t >= T_) return;
        int b3 = bid - 512;
        int bx = b3 & 3, by = (b3 >> 2) & 7, bz = b3 >> 5;
        const float* Hp = (t == 0) ? h1i : out + (size_t)(t - 1) * BFL;
        const float* Cp = (t == 0) ? c1i : c1s;
        lstm_body(Hp, W1,
                  Ax1 + (size_t)t * B_ * CO_ * L_, (size_t)CO_ * L_,
                  Cp, c1s, out + (size_t)t * BFL,
                  2 * F_, F_, bx, by, bz);
    }
}

// ---------------------------------------------------------------------------
extern "C" void kernel_launch(void* const* d_in, const int* in_sizes, int n_in,
                              void* d_out, int out_size)
{
    const float* x  = (const float*)d_in[0];  // [B, T, Cin, L]
    const float* W0 = (const float*)d_in[1];  // [512, 192, 5]
    const float* b0 = (const float*)d_in[2];  // [512]
    const float* W1 = (const float*)d_in[3];  // [512, 256, 5]
    const float* b1 = (const float*)d_in[4];  // [512]
    const float* h0 = (const float*)d_in[5];  // [B, F, L]
    const float* c0 = (const float*)d_in[6];
    const float* h1 = (const float*)d_in[7];
    const float* c1 = (const float*)d_in[8];
    float* out = (float*)d_out;               // [T, B, F, L]

    cudaFuncSetAttribute(wave_kernel,
                         cudaFuncAttributeMaxDynamicSharedMemorySize, CONV_SMEM);

    float *Ax0, *Ax1, *hs0, *c0s, *c1s;
    cudaGetSymbolAddress((void**)&Ax0, g_Ax0);
    cudaGetSymbolAddress((void**)&Ax1, g_Ax1);
    cudaGetSymbolAddress((void**)&hs0, g_hs0);
    cudaGetSymbolAddress((void**)&c0s, g_c0s);
    cudaGetSymbolAddress((void**)&c1s, g_c1s);

    for (int tau = -1; tau <= T_ + 1; tau++) {
        wave_kernel<<<768, 256, CONV_SMEM>>>(
            x, W0, b0, W1, b1, h0, c0, h1, c1,
            Ax0, Ax1, hs0, c0s, c1s, out, tau);
    }
}